// round 1
// baseline (speedup 1.0000x reference)
#include <cuda_runtime.h>
#include <cuda_bf16.h>
#include <cstdint>

// Problem constants
#define D      64        // embedding dim
#define KTOT   2048      // num embeddings
#define NROWS  65536     // 64*32*32 flattened rows
#define TK     64        // K-tile held in shared memory

// Output layout (concatenated fp32):
//   [0, 4194304)            quantized  (NROWS * D)
//   [4194304, 4259840)      encoding_indices as float (NROWS)
//   [4259840, 8454144)      flat_inputs (NROWS * D)
#define OFF_IDX   ((size_t)NROWS * D)
#define OFF_FLAT  ((size_t)NROWS * D + NROWS)

// Scratch: squared norms of embeddings (no cudaMalloc allowed)
__device__ float g_e2[KTOT];

// ---------------------------------------------------------------------------
// Kernel 1: e2[k] = sum_d emb[k][d]^2
// ---------------------------------------------------------------------------
__global__ void vq_e2_kernel(const float* __restrict__ emb) {
    int k = blockIdx.x * blockDim.x + threadIdx.x;
    if (k >= KTOT) return;
    const float4* e4 = reinterpret_cast<const float4*>(emb + (size_t)k * D);
    float s0 = 0.f, s1 = 0.f, s2 = 0.f, s3 = 0.f;
#pragma unroll
    for (int i = 0; i < D / 4; i++) {
        float4 v = e4[i];
        s0 = fmaf(v.x, v.x, s0);
        s1 = fmaf(v.y, v.y, s1);
        s2 = fmaf(v.z, v.z, s2);
        s3 = fmaf(v.w, v.w, s3);
    }
    g_e2[k] = (s0 + s1) + (s2 + s3);
}

// ---------------------------------------------------------------------------
// Kernel 2: per-row argmin over all K embeddings + write all three outputs.
// One thread = one input row. Embeddings streamed through shared memory in
// TK-sized tiles; all threads in a warp read the same shared address
// (broadcast, conflict-free). 4 accumulators break the FFMA RAW chain.
// ---------------------------------------------------------------------------
__global__ void __launch_bounds__(256, 2)
vq_main_kernel(const float* __restrict__ inp,
               const float* __restrict__ emb,
               float* __restrict__ out) {
    __shared__ float4 se[TK * (D / 4)];  // 64 embeddings x 64 floats = 16 KB
    __shared__ float  se2[TK];

    const int row = blockIdx.x * blockDim.x + threadIdx.x;  // < NROWS by grid

    // Load this thread's input row into registers (16 x float4 = 64 regs)
    float4 x[D / 4];
    const float4* xin = reinterpret_cast<const float4*>(inp + (size_t)row * D);
    float x2a = 0.f, x2b = 0.f, x2c = 0.f, x2d = 0.f;
#pragma unroll
    for (int i = 0; i < D / 4; i++) {
        x[i] = xin[i];
        x2a = fmaf(x[i].x, x[i].x, x2a);
        x2b = fmaf(x[i].y, x[i].y, x2b);
        x2c = fmaf(x[i].z, x[i].z, x2c);
        x2d = fmaf(x[i].w, x[i].w, x2d);
    }
    const float x2 = (x2a + x2b) + (x2c + x2d);

    float best = 3.402823466e+38f;  // FLT_MAX
    int   bi   = 0;

    for (int k0 = 0; k0 < KTOT; k0 += TK) {
        __syncthreads();
        // Cooperative tile load: TK*16 float4 by 256 threads -> 4 each
        const float4* eg = reinterpret_cast<const float4*>(emb + (size_t)k0 * D);
#pragma unroll
        for (int i = threadIdx.x; i < TK * (D / 4); i += 256) {
            se[i] = eg[i];
        }
        if (threadIdx.x < TK) se2[threadIdx.x] = g_e2[k0 + threadIdx.x];
        __syncthreads();

#pragma unroll 2
        for (int k = 0; k < TK; k++) {
            const float4* ek = &se[k * (D / 4)];
            float d0 = 0.f, d1 = 0.f, d2 = 0.f, d3 = 0.f;
#pragma unroll
            for (int i = 0; i < D / 4; i++) {
                float4 e = ek[i];
                d0 = fmaf(x[i].x, e.x, d0);
                d1 = fmaf(x[i].y, e.y, d1);
                d2 = fmaf(x[i].z, e.z, d2);
                d3 = fmaf(x[i].w, e.w, d3);
            }
            float dot  = (d0 + d1) + (d2 + d3);
            // Match reference expansion: (||x||^2 - 2 x.e) + ||e||^2
            float dist = (x2 - 2.0f * dot) + se2[k];
            // strict < with ascending k == first-index argmin (jnp semantics)
            if (dist < best) { best = dist; bi = k0 + k; }
        }
    }

    // --- outputs ---
    // quantized = embeddings[bi]   (gather; codebook is L2-resident: 512 KB)
    const float4* q  = reinterpret_cast<const float4*>(emb + (size_t)bi * D);
    float4*       oq = reinterpret_cast<float4*>(out + (size_t)row * D);
#pragma unroll
    for (int i = 0; i < D / 4; i++) oq[i] = q[i];

    // encoding index (as float, matching concatenated fp32 output buffer)
    out[OFF_IDX + row] = (float)bi;

    // flat_inputs = inputs (already in registers)
    float4* of = reinterpret_cast<float4*>(out + OFF_FLAT + (size_t)row * D);
#pragma unroll
    for (int i = 0; i < D / 4; i++) of[i] = x[i];
}

// ---------------------------------------------------------------------------
extern "C" void kernel_launch(void* const* d_in, const int* in_sizes, int n_in,
                              void* d_out, int out_size) {
    const float* inp = (const float*)d_in[0];   // [64,32,32,64] fp32
    const float* emb = (const float*)d_in[1];   // [2048,64]     fp32
    float* out = (float*)d_out;

    vq_e2_kernel<<<(KTOT + 255) / 256, 256>>>(emb);
    vq_main_kernel<<<NROWS / 256, 256>>>(inp, emb, out);
}

// round 2
// speedup vs baseline: 1.3723x; 1.3723x over previous
#include <cuda_runtime.h>
#include <cuda_bf16.h>
#include <cstdint>

// Problem constants
#define D      64        // embedding dim
#define KTOT   2048      // num embeddings
#define NROWS  65536     // 64*32*32 flattened rows
#define TK     64        // K-tile held in shared memory
#define BLOCK  128       // threads per block
#define RPT    2         // rows per thread
#define RPB    (BLOCK * RPT)   // 256 rows per block

// Output layout (concatenated fp32):
//   [0, 4194304)            quantized  (NROWS * D)
//   [4194304, 4259840)      encoding_indices as float (NROWS)
//   [4259840, 8454144)      flat_inputs (NROWS * D)
#define OFF_IDX   ((size_t)NROWS * D)
#define OFF_FLAT  ((size_t)NROWS * D + NROWS)

// Scratch: -(0.5 * ||e_k||^2)  (argmin dist == argmax (x.e - 0.5||e||^2))
__device__ float g_nh[KTOT];

typedef unsigned long long u64;

// Packed fp32x2 ops (SASS FFMA2 path, PTX-only)
#define FMA2(d, a, b, c) \
    asm("fma.rn.f32x2 %0, %1, %2, %3;" : "=l"(d) : "l"(a), "l"(b), "l"(c))
#define ADD2(d, a, b) \
    asm("add.rn.f32x2 %0, %1, %2;" : "=l"(d) : "l"(a), "l"(b))
#define UNPACK2(lo, hi, v) \
    asm("mov.b64 {%0, %1}, %2;" : "=f"(lo), "=f"(hi) : "l"(v))

// ---------------------------------------------------------------------------
// Kernel 1: g_nh[k] = -0.5 * sum_d emb[k][d]^2
// ---------------------------------------------------------------------------
__global__ void vq_e2_kernel(const float* __restrict__ emb) {
    int k = blockIdx.x * blockDim.x + threadIdx.x;
    if (k >= KTOT) return;
    const float4* e4 = reinterpret_cast<const float4*>(emb + (size_t)k * D);
    float s0 = 0.f, s1 = 0.f, s2 = 0.f, s3 = 0.f;
#pragma unroll
    for (int i = 0; i < D / 4; i++) {
        float4 v = e4[i];
        s0 = fmaf(v.x, v.x, s0);
        s1 = fmaf(v.y, v.y, s1);
        s2 = fmaf(v.z, v.z, s2);
        s3 = fmaf(v.w, v.w, s3);
    }
    g_nh[k] = -0.5f * ((s0 + s1) + (s2 + s3));
}

// ---------------------------------------------------------------------------
// Kernel 2: each thread owns 2 rows (register-resident, packed f32x2).
// Embedding tiles stream through shared memory; all lanes broadcast-read the
// same embedding, amortized over 2 rows. Inner product via FFMA2 (4 chains).
// ---------------------------------------------------------------------------
__global__ void __launch_bounds__(BLOCK)
vq_main_kernel(const float* __restrict__ inp,
               const float* __restrict__ emb,
               float* __restrict__ out) {
    __shared__ __align__(16) u64 se[TK * (D / 2)];  // 64 emb x 64 f32 = 16 KB
    __shared__ float snh[TK];

    const int t    = threadIdx.x;
    const int row0 = blockIdx.x * RPB + t;       // rows [blk*256 + t]
    const int row1 = row0 + BLOCK;               //      [blk*256 + t + 128]

    // Load both input rows into registers as packed f32x2 (64 regs each)
    u64 x0[D / 2], x1[D / 2];
    {
        const ulonglong2* p0 = reinterpret_cast<const ulonglong2*>(inp + (size_t)row0 * D);
        const ulonglong2* p1 = reinterpret_cast<const ulonglong2*>(inp + (size_t)row1 * D);
#pragma unroll
        for (int i = 0; i < D / 4; i++) {
            ulonglong2 v = p0[i];
            x0[2 * i] = v.x; x0[2 * i + 1] = v.y;
        }
#pragma unroll
        for (int i = 0; i < D / 4; i++) {
            ulonglong2 v = p1[i];
            x1[2 * i] = v.x; x1[2 * i + 1] = v.y;
        }
    }

    float best0 = -3.402823466e+38f, best1 = -3.402823466e+38f;
    int   bi0 = 0, bi1 = 0;

    for (int k0 = 0; k0 < KTOT; k0 += TK) {
        __syncthreads();
        // Cooperative tile load: 1024 float4 by 128 threads -> 8 each
        const float4* eg = reinterpret_cast<const float4*>(emb + (size_t)k0 * D);
        float4* s4 = reinterpret_cast<float4*>(se);
#pragma unroll
        for (int i = t; i < TK * (D / 4); i += BLOCK) s4[i] = eg[i];
        if (t < TK) snh[t] = g_nh[k0 + t];
        __syncthreads();

#pragma unroll 2
        for (int k = 0; k < TK; k++) {
            const u64* ek = &se[k * (D / 2)];
            u64 a0 = 0ull, b0 = 0ull, a1 = 0ull, b1 = 0ull;  // packed (0,0)
#pragma unroll
            for (int i = 0; i < D / 4; i++) {
                u64 e01 = ek[2 * i];
                u64 e23 = ek[2 * i + 1];
                FMA2(a0, x0[2 * i],     e01, a0);
                FMA2(b0, x0[2 * i + 1], e23, b0);
                FMA2(a1, x1[2 * i],     e01, a1);
                FMA2(b1, x1[2 * i + 1], e23, b1);
            }
            u64 s0, s1;
            ADD2(s0, a0, b0);
            ADD2(s1, a1, b1);
            float lo0, hi0, lo1, hi1;
            UNPACK2(lo0, hi0, s0);
            UNPACK2(lo1, hi1, s1);
            const float nh = snh[k];
            // score = x.e - 0.5||e||^2 ; maximize. argmax(score) == argmin(dist)
            float sc0 = (lo0 + hi0) + nh;
            float sc1 = (lo1 + hi1) + nh;
            // strict > keeps the FIRST (lowest-index) maximum == jnp.argmin
            if (sc0 > best0) { best0 = sc0; bi0 = k0 + k; }
            if (sc1 > best1) { best1 = sc1; bi1 = k0 + k; }
        }
    }

    // --- outputs ---
    // quantized = embeddings[bi]  (gather; 512 KB codebook is L2-resident)
    {
        const float4* q0 = reinterpret_cast<const float4*>(emb + (size_t)bi0 * D);
        const float4* q1 = reinterpret_cast<const float4*>(emb + (size_t)bi1 * D);
        float4* o0 = reinterpret_cast<float4*>(out + (size_t)row0 * D);
        float4* o1 = reinterpret_cast<float4*>(out + (size_t)row1 * D);
#pragma unroll
        for (int i = 0; i < D / 4; i++) o0[i] = q0[i];
#pragma unroll
        for (int i = 0; i < D / 4; i++) o1[i] = q1[i];
    }

    // encoding indices as float
    out[OFF_IDX + row0] = (float)bi0;
    out[OFF_IDX + row1] = (float)bi1;

    // flat_inputs = inputs (already in registers as packed pairs)
    {
        ulonglong2* f0 = reinterpret_cast<ulonglong2*>(out + OFF_FLAT + (size_t)row0 * D);
        ulonglong2* f1 = reinterpret_cast<ulonglong2*>(out + OFF_FLAT + (size_t)row1 * D);
#pragma unroll
        for (int i = 0; i < D / 4; i++) {
            ulonglong2 v; v.x = x0[2 * i]; v.y = x0[2 * i + 1];
            f0[i] = v;
        }
#pragma unroll
        for (int i = 0; i < D / 4; i++) {
            ulonglong2 v; v.x = x1[2 * i]; v.y = x1[2 * i + 1];
            f1[i] = v;
        }
    }
}

// ---------------------------------------------------------------------------
extern "C" void kernel_launch(void* const* d_in, const int* in_sizes, int n_in,
                              void* d_out, int out_size) {
    const float* inp = (const float*)d_in[0];   // [64,32,32,64] fp32
    const float* emb = (const float*)d_in[1];   // [2048,64]     fp32
    float* out = (float*)d_out;

    vq_e2_kernel<<<(KTOT + 255) / 256, 256>>>(emb);
    vq_main_kernel<<<NROWS / RPB, BLOCK>>>(inp, emb, out);
}

// round 3
// speedup vs baseline: 1.4356x; 1.0462x over previous
#include <cuda_runtime.h>
#include <cuda_bf16.h>
#include <cstdint>

// Problem constants
#define D      64        // embedding dim
#define KTOT   2048      // num embeddings
#define KHALF  1024      // split-K: each block scans half the codebook
#define NROWS  65536     // 64*32*32 flattened rows
#define TK     64        // K-tile held in shared memory
#define BLOCK  128       // threads per block
#define RPT    2         // rows per thread
#define RPB    (BLOCK * RPT)   // 256 rows per block
#define NCHUNK (NROWS / RPB)   // 256 row-chunks

// Output layout (concatenated fp32):
//   [0, 4194304)            quantized  (NROWS * D)
//   [4194304, 4259840)      encoding_indices as float (NROWS)
//   [4259840, 8454144)      flat_inputs (NROWS * D)
#define OFF_IDX   ((size_t)NROWS * D)
#define OFF_FLAT  ((size_t)NROWS * D + NROWS)

// Scratch (device globals; no cudaMalloc allowed)
__device__ float g_nh[KTOT];            // -(0.5 * ||e_k||^2)
__device__ float g_ps[2][NROWS];        // partial best score per half
__device__ int   g_pi[2][NROWS];        // partial best index per half

typedef unsigned long long u64;

// Packed fp32x2 ops (SASS FFMA2 path, PTX-only)
#define FMA2(d, a, b, c) \
    asm("fma.rn.f32x2 %0, %1, %2, %3;" : "=l"(d) : "l"(a), "l"(b), "l"(c))
#define ADD2(d, a, b) \
    asm("add.rn.f32x2 %0, %1, %2;" : "=l"(d) : "l"(a), "l"(b))
#define UNPACK2(lo, hi, v) \
    asm("mov.b64 {%0, %1}, %2;" : "=f"(lo), "=f"(hi) : "l"(v))
#define PACK2(d, lo, hi) \
    asm("mov.b64 %0, {%1, %2};" : "=l"(d) : "f"(lo), "f"(hi))

// ---------------------------------------------------------------------------
// Kernel 1: g_nh[k] = -0.5 * sum_d emb[k][d]^2
// ---------------------------------------------------------------------------
__global__ void vq_e2_kernel(const float* __restrict__ emb) {
    int k = blockIdx.x * blockDim.x + threadIdx.x;
    if (k >= KTOT) return;
    const float4* e4 = reinterpret_cast<const float4*>(emb + (size_t)k * D);
    float s0 = 0.f, s1 = 0.f, s2 = 0.f, s3 = 0.f;
#pragma unroll
    for (int i = 0; i < D / 4; i++) {
        float4 v = e4[i];
        s0 = fmaf(v.x, v.x, s0);
        s1 = fmaf(v.y, v.y, s1);
        s2 = fmaf(v.z, v.z, s2);
        s3 = fmaf(v.w, v.w, s3);
    }
    g_nh[k] = -0.5f * ((s0 + s1) + (s2 + s3));
}

// ---------------------------------------------------------------------------
// Kernel 2 (hot): split-K partial argmax of score = x.e - 0.5||e||^2.
// grid = NCHUNK * 2 blocks; block b handles row-chunk (b>>1), K-half (b&1).
// Each thread owns 2 rows in registers (packed f32x2, FFMA2 inner product).
// ---------------------------------------------------------------------------
__global__ void __launch_bounds__(BLOCK, 3)
vq_main_kernel(const float* __restrict__ inp,
               const float* __restrict__ emb) {
    __shared__ __align__(16) u64 se[TK * (D / 2)];  // 64 emb x 64 f32 = 16 KB
    __shared__ float snh[TK];

    const int t     = threadIdx.x;
    const int chunk = blockIdx.x >> 1;
    const int half  = blockIdx.x & 1;
    const int koff  = half * KHALF;
    const int row0  = chunk * RPB + t;
    const int row1  = row0 + BLOCK;

    // Load both input rows into registers as packed f32x2 (64 regs each)
    u64 x0[D / 2], x1[D / 2];
    {
        const ulonglong2* p0 = reinterpret_cast<const ulonglong2*>(inp + (size_t)row0 * D);
        const ulonglong2* p1 = reinterpret_cast<const ulonglong2*>(inp + (size_t)row1 * D);
#pragma unroll
        for (int i = 0; i < D / 4; i++) {
            ulonglong2 v = p0[i];
            x0[2 * i] = v.x; x0[2 * i + 1] = v.y;
        }
#pragma unroll
        for (int i = 0; i < D / 4; i++) {
            ulonglong2 v = p1[i];
            x1[2 * i] = v.x; x1[2 * i + 1] = v.y;
        }
    }

    float best0 = -3.402823466e+38f, best1 = -3.402823466e+38f;
    int   bi0 = koff, bi1 = koff;

    for (int k0 = koff; k0 < koff + KHALF; k0 += TK) {
        __syncthreads();
        // Cooperative tile load: 1024 float4 by 128 threads -> 8 each
        const float4* eg = reinterpret_cast<const float4*>(emb + (size_t)k0 * D);
        float4* s4 = reinterpret_cast<float4*>(se);
#pragma unroll
        for (int i = t; i < TK * (D / 4); i += BLOCK) s4[i] = eg[i];
        if (t < TK) snh[t] = g_nh[k0 + t];
        __syncthreads();

#pragma unroll 2
        for (int k = 0; k < TK; k++) {
            const u64* ek = &se[k * (D / 2)];
            const float nh = snh[k];
            u64 a0, a1;
            PACK2(a0, nh, 0.f);          // fold -0.5||e||^2 into the accumulator
            a1 = a0;
            u64 b0 = 0ull, b1 = 0ull;
#pragma unroll
            for (int i = 0; i < D / 4; i++) {
                u64 e01 = ek[2 * i];
                u64 e23 = ek[2 * i + 1];
                FMA2(a0, x0[2 * i],     e01, a0);
                FMA2(b0, x0[2 * i + 1], e23, b0);
                FMA2(a1, x1[2 * i],     e01, a1);
                FMA2(b1, x1[2 * i + 1], e23, b1);
            }
            u64 s0, s1;
            ADD2(s0, a0, b0);
            ADD2(s1, a1, b1);
            float lo0, hi0, lo1, hi1;
            UNPACK2(lo0, hi0, s0);
            UNPACK2(lo1, hi1, s1);
            float sc0 = lo0 + hi0;
            float sc1 = lo1 + hi1;
            // strict > keeps the FIRST (lowest-index) maximum == jnp.argmin
            if (sc0 > best0) { best0 = sc0; bi0 = k0 + k; }
            if (sc1 > best1) { best1 = sc1; bi1 = k0 + k; }
        }
    }

    g_ps[half][row0] = best0;  g_pi[half][row0] = bi0;
    g_ps[half][row1] = best1;  g_pi[half][row1] = bi1;
}

// ---------------------------------------------------------------------------
// Kernel 3: combine halves + emit all outputs. 16 threads per row (one float4
// chunk each) -> fully coalesced. Ties across halves go to half 0 (lower
// indices), matching jnp.argmin first-index semantics.
// ---------------------------------------------------------------------------
__global__ void __launch_bounds__(256)
vq_combine_kernel(const float* __restrict__ inp,
                  const float* __restrict__ emb,
                  float* __restrict__ out) {
    const int tid = blockIdx.x * blockDim.x + threadIdx.x;  // NROWS*16 total
    const int row = tid >> 4;
    const int c   = tid & 15;

    const float s0 = g_ps[0][row];
    const float s1 = g_ps[1][row];
    const int   bi = (s1 > s0) ? g_pi[1][row] : g_pi[0][row];

    // quantized = embeddings[bi]  (512 KB codebook stays L2-resident)
    const float4 q = reinterpret_cast<const float4*>(emb + (size_t)bi * D)[c];
    reinterpret_cast<float4*>(out + (size_t)row * D)[c] = q;

    // flat_inputs = inputs
    const float4 xi = reinterpret_cast<const float4*>(inp + (size_t)row * D)[c];
    reinterpret_cast<float4*>(out + OFF_FLAT + (size_t)row * D)[c] = xi;

    if (c == 0) out[OFF_IDX + row] = (float)bi;
}

// ---------------------------------------------------------------------------
extern "C" void kernel_launch(void* const* d_in, const int* in_sizes, int n_in,
                              void* d_out, int out_size) {
    const float* inp = (const float*)d_in[0];   // [64,32,32,64] fp32
    const float* emb = (const float*)d_in[1];   // [2048,64]     fp32
    float* out = (float*)d_out;

    vq_e2_kernel<<<(KTOT + 255) / 256, 256>>>(emb);
    vq_main_kernel<<<NCHUNK * 2, BLOCK>>>(inp, emb);
    vq_combine_kernel<<<(NROWS * 16) / 256, 256>>>(inp, emb, out);
}

// round 5
// speedup vs baseline: 1.8281x; 1.2734x over previous
#include <cuda_runtime.h>
#include <cuda_bf16.h>
#include <cstdint>

// ---------------------------------------------------------------------------
// Problem constants
// ---------------------------------------------------------------------------
#define D       64
#define KTOT    2048
#define NROWS   65536
#define KDIM    192                  // GEMM K: [X0,X0,X1] x [E0,E1,E0]
#define M_BLK   128
#define NSUB    64
#define NSUBS   (KTOT / NSUB)        // 32
#define NBLOCKS (NROWS / M_BLK)      // 512
#define THRESH  (1.0f / 128.0f)      // > 2x worst-case approx error

// Output layout (concatenated fp32)
#define OFF_IDX  ((size_t)NROWS * D)
#define OFF_FLAT ((size_t)NROWS * D + NROWS)

// smem layout (bytes), row stride 400B (=200 bf16) for conflict-free ldmatrix
#define SA_BYTES   400
#define SM_A       0
#define SM_B0      (128 * SA_BYTES)                 // 51200
#define SM_B1      (SM_B0 + 64 * SA_BYTES)          // 76800
#define SM_NH0     (SM_B1 + 64 * SA_BYTES)          // 102400
#define SM_NH1     (SM_NH0 + 256)                   // 102656
#define SMEM_TOTAL (SM_NH1 + 256)                   // 102912

// ---------------------------------------------------------------------------
// Device scratch (no cudaMalloc allowed)
// ---------------------------------------------------------------------------
__device__ unsigned g_A[NROWS * (KDIM / 2)];   // A' packed bf16x2, 25 MB
__device__ unsigned g_B[KTOT  * (KDIM / 2)];   // B' packed bf16x2, 768 KB
__device__ float    g_nh[KTOT];                // -0.5*||e_k||^2
__device__ int      g_bi[NROWS];
__device__ int      g_rlist[NROWS];
__device__ int      g_rcnt;

// ---------------------------------------------------------------------------
// PTX helpers (all baseline sm_80+, safe for compute_103)
// ---------------------------------------------------------------------------
__device__ __forceinline__ uint32_t smem_u32(const void* p) {
    uint32_t a;
    asm("{ .reg .u64 t; cvta.to.shared.u64 t, %1; cvt.u32.u64 %0, t; }" : "=r"(a) : "l"(p));
    return a;
}
__device__ __forceinline__ void cpa16(uint32_t dst, const void* src) {
    asm volatile("cp.async.cg.shared.global [%0], [%1], 16;" :: "r"(dst), "l"(src));
}
#define CP_COMMIT() asm volatile("cp.async.commit_group;" ::: "memory")
#define CP_WAIT0()  asm volatile("cp.async.wait_group 0;" ::: "memory")

#define LDSM4(r0, r1, r2, r3, addr)                                           \
    asm volatile("ldmatrix.sync.aligned.m8n8.x4.shared.b16 {%0,%1,%2,%3}, [%4];" \
                 : "=r"(r0), "=r"(r1), "=r"(r2), "=r"(r3) : "r"(addr))

#define MMA16816(c, a0, a1, a2, a3, b0, b1)                                   \
    asm volatile("mma.sync.aligned.m16n8k16.row.col.f32.bf16.bf16.f32 "       \
                 "{%0,%1,%2,%3}, {%4,%5,%6,%7}, {%8,%9}, {%0,%1,%2,%3};"      \
                 : "+f"((c)[0]), "+f"((c)[1]), "+f"((c)[2]), "+f"((c)[3])     \
                 : "r"(a0), "r"(a1), "r"(a2), "r"(a3), "r"(b0), "r"(b1))

// ---------------------------------------------------------------------------
// Exact 2-way bf16 split: x = f0 + f1 + O(2^-18 |x|)
// ---------------------------------------------------------------------------
__device__ __forceinline__ void split2(float x, unsigned short& s0, unsigned short& s1) {
    __nv_bfloat16 h0 = __float2bfloat16_rn(x);
    float r = x - __bfloat162float(h0);        // exact (Sterbenz)
    __nv_bfloat16 h1 = __float2bfloat16_rn(r);
    s0 = __bfloat16_as_ushort(h0);
    s1 = __bfloat16_as_ushort(h1);
}

// ---------------------------------------------------------------------------
// Prep: A' rows = [X0 | X0 | X1]  (packed bf16x2; 96 u32 per row)
// ---------------------------------------------------------------------------
__global__ void vq_split_x(const float* __restrict__ inp) {
    int i = blockIdx.x * blockDim.x + threadIdx.x;   // NROWS*32 threads
    float2 v = reinterpret_cast<const float2*>(inp)[i];
    unsigned short a0, a1, b0, b1;
    split2(v.x, a0, a1);
    split2(v.y, b0, b1);
    unsigned p0 = (unsigned)a0 | ((unsigned)b0 << 16);
    unsigned p1 = (unsigned)a1 | ((unsigned)b1 << 16);
    int row = i >> 5, d2 = i & 31;
    unsigned* base = g_A + (size_t)row * 96;
    base[d2]      = p0;
    base[32 + d2] = p0;
    base[64 + d2] = p1;
}

// Prep: B' rows = [E0 | E1 | E0]
__global__ void vq_split_e(const float* __restrict__ emb) {
    int i = blockIdx.x * blockDim.x + threadIdx.x;   // KTOT*32 threads
    float2 v = reinterpret_cast<const float2*>(emb)[i];
    unsigned short a0, a1, b0, b1;
    split2(v.x, a0, a1);
    split2(v.y, b0, b1);
    unsigned p0 = (unsigned)a0 | ((unsigned)b0 << 16);
    unsigned p1 = (unsigned)a1 | ((unsigned)b1 << 16);
    int k = i >> 5, d2 = i & 31;
    unsigned* base = g_B + (size_t)k * 96;
    base[d2]      = p0;
    base[32 + d2] = p1;
    base[64 + d2] = p0;
}

// Prep: nh[k] = -0.5*||e_k||^2 ; also reset rescue counter
__global__ void vq_nh_kernel(const float* __restrict__ emb) {
    int k = blockIdx.x * blockDim.x + threadIdx.x;
    if (k == 0) g_rcnt = 0;
    if (k >= KTOT) return;
    const float4* e4 = reinterpret_cast<const float4*>(emb + (size_t)k * D);
    float s0 = 0.f, s1 = 0.f, s2 = 0.f, s3 = 0.f;
#pragma unroll
    for (int i = 0; i < D / 4; i++) {
        float4 v = e4[i];
        s0 = fmaf(v.x, v.x, s0);
        s1 = fmaf(v.y, v.y, s1);
        s2 = fmaf(v.z, v.z, s2);
        s3 = fmaf(v.w, v.w, s3);
    }
    g_nh[k] = -0.5f * ((s0 + s1) + (s2 + s3));
}

// ---------------------------------------------------------------------------
// top-2 update (ascending idx order per thread; strict > => lowest idx wins)
// ---------------------------------------------------------------------------
__device__ __forceinline__ void upd(float& b1, float& b2, int& i1, float v, int idx) {
    if (v > b1) { b2 = b1; b1 = v; i1 = idx; }
    else        { b2 = fmaxf(b2, v); }
}

// ---------------------------------------------------------------------------
// Main kernel: 128 rows/block; approx score GEMM via mma.sync bf16 (K=192)
// with fused per-row top-2 argmax; close rows flagged for exact rescue.
// ---------------------------------------------------------------------------
__global__ void __launch_bounds__(256, 2) vq_mma_kernel() {
    extern __shared__ __align__(16) char smem[];
    const uint32_t SB  = smem_u32(smem);
    const int tid  = threadIdx.x;
    const int lane = tid & 31;
    const int wid  = tid >> 5;
    const int row0blk = blockIdx.x * M_BLK;

    const uint32_t smA  = SB + SM_A;
    const uint32_t smB[2] = { SB + SM_B0, SB + SM_B1 };
    float* nhbuf[2] = { (float*)(smem + SM_NH0), (float*)(smem + SM_NH1) };

    // ---- prologue: async-load A tile (128x192) and B subtile 0 + nh0 ----
    {
        const char* gA = (const char*)(g_A + (size_t)row0blk * 96);
#pragma unroll
        for (int i = tid; i < 128 * 24; i += 256) {
            int r = i / 24, c = i - r * 24;
            cpa16(smA + r * SA_BYTES + c * 16, gA + (size_t)r * 384 + c * 16);
        }
        const char* gB = (const char*)g_B;
#pragma unroll
        for (int i = tid; i < 64 * 24; i += 256) {
            int r = i / 24, c = i - r * 24;
            cpa16(smB[0] + r * SA_BYTES + c * 16, gB + (size_t)r * 384 + c * 16);
        }
        if (tid < 64) nhbuf[0][tid] = g_nh[tid];
        CP_COMMIT();
        CP_WAIT0();
        __syncthreads();
    }

    // ldmatrix address components
    const uint32_t aAddr = smA + (wid * 16 + (lane & 15)) * SA_BYTES + (lane >> 4) * 16;
    const int q        = lane >> 3;
    const int brow     = ((q >> 1) * 8) + (lane & 7);
    const uint32_t bk  = (q & 1) * 16;

    // persistent top-2 state for the 2 rows this thread touches
    float b1a = -3.402823466e+38f, b2a = -3.402823466e+38f;
    float b1b = -3.402823466e+38f, b2b = -3.402823466e+38f;
    int   i1a = 0, i1b = 0;

    for (int s = 0; s < NSUBS; s++) {
        const int buf = s & 1;
        // prefetch next B subtile + nh into the other buffer
        if (s + 1 < NSUBS) {
            const char* gB = (const char*)(g_B + (size_t)(s + 1) * 64 * 96);
#pragma unroll
            for (int i = tid; i < 64 * 24; i += 256) {
                int r = i / 24, c = i - r * 24;
                cpa16(smB[buf ^ 1] + r * SA_BYTES + c * 16, gB + (size_t)r * 384 + c * 16);
            }
            if (tid < 64) nhbuf[buf ^ 1][tid] = g_nh[(s + 1) * 64 + tid];
            CP_COMMIT();
        }

        // ---- compute: 12 k-steps x 8 n8-tiles ----
        float c[8][4];
#pragma unroll
        for (int j = 0; j < 8; j++) { c[j][0] = c[j][1] = c[j][2] = c[j][3] = 0.f; }

        const uint32_t bb = smB[buf];
#pragma unroll
        for (int k = 0; k < 12; k++) {
            uint32_t a0, a1, a2, a3;
            LDSM4(a0, a1, a2, a3, aAddr + k * 32);
#pragma unroll
            for (int t = 0; t < 4; t++) {
                uint32_t r0, r1, r2, r3;
                LDSM4(r0, r1, r2, r3, bb + (t * 16 + brow) * SA_BYTES + bk + k * 32);
                MMA16816(c[2 * t],     a0, a1, a2, a3, r0, r1);
                MMA16816(c[2 * t + 1], a0, a1, a2, a3, r2, r3);
            }
        }

        // ---- epilogue: add nh, update top-2 (cols ascending) ----
        const float* snh = nhbuf[buf];
        const int cb = s * NSUB;
#pragma unroll
        for (int j = 0; j < 8; j++) {
            const int lc = j * 8 + 2 * (lane & 3);
            const float nh0 = snh[lc], nh1 = snh[lc + 1];
            const int gi = cb + lc;
            upd(b1a, b2a, i1a, c[j][0] + nh0, gi);
            upd(b1a, b2a, i1a, c[j][1] + nh1, gi + 1);
            upd(b1b, b2b, i1b, c[j][2] + nh0, gi);
            upd(b1b, b2b, i1b, c[j][3] + nh1, gi + 1);
        }

        if (s + 1 < NSUBS) {
            CP_WAIT0();
            __syncthreads();
        }
    }

    // ---- merge top-2 across the 4 lanes sharing each row ----
#pragma unroll
    for (int m = 1; m <= 2; m <<= 1) {
        float ob1 = __shfl_xor_sync(0xffffffffu, b1a, m);
        float ob2 = __shfl_xor_sync(0xffffffffu, b2a, m);
        int   oi1 = __shfl_xor_sync(0xffffffffu, i1a, m);
        if (ob1 > b1a || (ob1 == b1a && oi1 < i1a)) { b2a = fmaxf(b1a, ob2); b1a = ob1; i1a = oi1; }
        else                                        { b2a = fmaxf(b2a, ob1); }
        ob1 = __shfl_xor_sync(0xffffffffu, b1b, m);
        ob2 = __shfl_xor_sync(0xffffffffu, b2b, m);
        oi1 = __shfl_xor_sync(0xffffffffu, i1b, m);
        if (ob1 > b1b || (ob1 == b1b && oi1 < i1b)) { b2b = fmaxf(b1b, ob2); b1b = ob1; i1b = oi1; }
        else                                        { b2b = fmaxf(b2b, ob1); }
    }

    if ((lane & 3) == 0) {
        const int ra = row0blk + wid * 16 + (lane >> 2);
        const int rb = ra + 8;
        g_bi[ra] = i1a;
        g_bi[rb] = i1b;
        if (b1a - b2a < THRESH) { int p = atomicAdd(&g_rcnt, 1); g_rlist[p] = ra; }
        if (b1b - b2b < THRESH) { int p = atomicAdd(&g_rcnt, 1); g_rlist[p] = rb; }
    }
}

// ---------------------------------------------------------------------------
// Rescue: exact fp32 full rescan for flagged rows (warp per row)
// ---------------------------------------------------------------------------
#define RES_BLOCKS 256
__global__ void __launch_bounds__(256)
vq_rescue_kernel(const float* __restrict__ inp, const float* __restrict__ emb) {
    const int lane = threadIdx.x & 31;
    const int gw   = (blockIdx.x * blockDim.x + threadIdx.x) >> 5;
    const int nw   = RES_BLOCKS * 256 / 32;
    const int cnt  = g_rcnt;

    for (int i = gw; i < cnt; i += nw) {
        const int row = g_rlist[i];
        float4 x[16];
        const float4* xr = reinterpret_cast<const float4*>(inp + (size_t)row * D);
#pragma unroll
        for (int j = 0; j < 16; j++) x[j] = xr[j];

        float best = -3.402823466e+38f;
        int   bi   = 0;
        for (int k = lane; k < KTOT; k += 32) {
            const float4* er = reinterpret_cast<const float4*>(emb + (size_t)k * D);
            float d0 = 0.f, d1 = 0.f, d2 = 0.f, d3 = 0.f;
#pragma unroll
            for (int j = 0; j < 16; j++) {
                float4 e = er[j];
                d0 = fmaf(x[j].x, e.x, d0);
                d1 = fmaf(x[j].y, e.y, d1);
                d2 = fmaf(x[j].z, e.z, d2);
                d3 = fmaf(x[j].w, e.w, d3);
            }
            float sc = ((d0 + d1) + (d2 + d3)) + g_nh[k];
            if (sc > best) { best = sc; bi = k; }   // ascending per lane
        }
#pragma unroll
        for (int m = 16; m >= 1; m >>= 1) {
            float ob = __shfl_xor_sync(0xffffffffu, best, m);
            int   oi = __shfl_xor_sync(0xffffffffu, bi, m);
            if (ob > best || (ob == best && oi < bi)) { best = ob; bi = oi; }
        }
        if (lane == 0) g_bi[row] = bi;
    }
}

// ---------------------------------------------------------------------------
// Combine: emit all three outputs, fully coalesced (16 threads per row)
// ---------------------------------------------------------------------------
__global__ void __launch_bounds__(256)
vq_combine_kernel(const float* __restrict__ inp,
                  const float* __restrict__ emb,
                  float* __restrict__ out) {
    const int t   = blockIdx.x * blockDim.x + threadIdx.x;   // NROWS*16
    const int row = t >> 4;
    const int c   = t & 15;
    const int bi  = g_bi[row];

    const float4 qv = reinterpret_cast<const float4*>(emb + (size_t)bi * D)[c];
    reinterpret_cast<float4*>(out + (size_t)row * D)[c] = qv;

    const float4 xi = reinterpret_cast<const float4*>(inp + (size_t)row * D)[c];
    reinterpret_cast<float4*>(out + OFF_FLAT + (size_t)row * D)[c] = xi;

    if (c == 0) out[OFF_IDX + row] = (float)bi;
}

// ---------------------------------------------------------------------------
extern "C" void kernel_launch(void* const* d_in, const int* in_sizes, int n_in,
                              void* d_out, int out_size) {
    const float* inp = (const float*)d_in[0];   // [64,32,32,64] fp32
    const float* emb = (const float*)d_in[1];   // [2048,64]     fp32
    float* out = (float*)d_out;

    static int smem_set = 0;
    if (!smem_set) {
        cudaFuncSetAttribute(vq_mma_kernel,
                             cudaFuncAttributeMaxDynamicSharedMemorySize, SMEM_TOTAL);
        smem_set = 1;
    }

    vq_split_x<<<NROWS * 32 / 256, 256>>>(inp);
    vq_split_e<<<KTOT * 32 / 256, 256>>>(emb);
    vq_nh_kernel<<<(KTOT + 255) / 256, 256>>>(emb);
    vq_mma_kernel<<<NBLOCKS, 256, SMEM_TOTAL>>>();
    vq_rescue_kernel<<<RES_BLOCKS, 256>>>(inp, emb);
    vq_combine_kernel<<<NROWS * 16 / 256, 256>>>(inp, emb, out);
}

// round 6
// speedup vs baseline: 1.8793x; 1.0280x over previous
#include <cuda_runtime.h>
#include <cuda_bf16.h>
#include <cstdint>

// ---------------------------------------------------------------------------
// Problem constants
// ---------------------------------------------------------------------------
#define D       64
#define KTOT    2048
#define NROWS   65536
#define KDIM    192                  // GEMM K: [X0,X0,X1] x [E0,E1,E0]
#define M_BLK   256                  // rows per block (32 per warp)
#define NSUB    64
#define NSUBS   (KTOT / NSUB)        // 32
#define NBLOCKS (NROWS / M_BLK)      // 256
#define THRESH  (1.0f / 128.0f)      // > 2x worst-case approx error

// Output layout (concatenated fp32)
#define OFF_IDX  ((size_t)NROWS * D)
#define OFF_FLAT ((size_t)NROWS * D + NROWS)

// smem layout (bytes); row stride 400B for conflict-free ldmatrix
#define SA_BYTES   400
#define SM_A       0
#define SM_B0      (M_BLK * SA_BYTES)               // 102400
#define SM_B1      (SM_B0 + 64 * SA_BYTES)          // 128000
#define SM_NH0     (SM_B1 + 64 * SA_BYTES)          // 153600
#define SM_NH1     (SM_NH0 + 256)                   // 153856
#define SMEM_TOTAL (SM_NH1 + 256)                   // 154112

// ---------------------------------------------------------------------------
// Device scratch (no cudaMalloc allowed)
// ---------------------------------------------------------------------------
__device__ unsigned g_B[KTOT * (KDIM / 2)];   // B' packed bf16x2, 768 KB (L2-resident)
__device__ float    g_nh[KTOT];               // -0.5*||e_k||^2
__device__ int      g_bi[NROWS];
__device__ int      g_rlist[NROWS];
__device__ int      g_rcnt;

// ---------------------------------------------------------------------------
// PTX helpers (all baseline sm_80+, safe for compute_103)
// ---------------------------------------------------------------------------
__device__ __forceinline__ uint32_t smem_u32(const void* p) {
    uint32_t a;
    asm("{ .reg .u64 t; cvta.to.shared.u64 t, %1; cvt.u32.u64 %0, t; }" : "=r"(a) : "l"(p));
    return a;
}
__device__ __forceinline__ void cpa16(uint32_t dst, const void* src) {
    asm volatile("cp.async.cg.shared.global [%0], [%1], 16;" :: "r"(dst), "l"(src));
}
#define CP_COMMIT() asm volatile("cp.async.commit_group;" ::: "memory")
#define CP_WAIT0()  asm volatile("cp.async.wait_group 0;" ::: "memory")

#define LDSM4(r0, r1, r2, r3, addr)                                           \
    asm volatile("ldmatrix.sync.aligned.m8n8.x4.shared.b16 {%0,%1,%2,%3}, [%4];" \
                 : "=r"(r0), "=r"(r1), "=r"(r2), "=r"(r3) : "r"(addr))

#define MMA16816(c, a0, a1, a2, a3, b0, b1)                                   \
    asm volatile("mma.sync.aligned.m16n8k16.row.col.f32.bf16.bf16.f32 "       \
                 "{%0,%1,%2,%3}, {%4,%5,%6,%7}, {%8,%9}, {%0,%1,%2,%3};"      \
                 : "+f"((c)[0]), "+f"((c)[1]), "+f"((c)[2]), "+f"((c)[3])     \
                 : "r"(a0), "r"(a1), "r"(a2), "r"(a3), "r"(b0), "r"(b1))

// ---------------------------------------------------------------------------
// Exact 2-way bf16 split: x = f0 + f1 + O(2^-18 |x|)
// ---------------------------------------------------------------------------
__device__ __forceinline__ void split2(float x, unsigned short& s0, unsigned short& s1) {
    __nv_bfloat16 h0 = __float2bfloat16_rn(x);
    float r = x - __bfloat162float(h0);        // exact (Sterbenz)
    __nv_bfloat16 h1 = __float2bfloat16_rn(r);
    s0 = __bfloat16_as_ushort(h0);
    s1 = __bfloat16_as_ushort(h1);
}

// Prep: B' rows = [E0 | E1 | E0]
__global__ void vq_split_e(const float* __restrict__ emb) {
    int i = blockIdx.x * blockDim.x + threadIdx.x;   // KTOT*32 threads
    float2 v = reinterpret_cast<const float2*>(emb)[i];
    unsigned short a0, a1, b0, b1;
    split2(v.x, a0, a1);
    split2(v.y, b0, b1);
    unsigned p0 = (unsigned)a0 | ((unsigned)b0 << 16);
    unsigned p1 = (unsigned)a1 | ((unsigned)b1 << 16);
    int k = i >> 5, d2 = i & 31;
    unsigned* base = g_B + (size_t)k * 96;
    base[d2]      = p0;
    base[32 + d2] = p1;
    base[64 + d2] = p0;
}

// Prep: nh[k] = -0.5*||e_k||^2 ; also reset rescue counter
__global__ void vq_nh_kernel(const float* __restrict__ emb) {
    int k = blockIdx.x * blockDim.x + threadIdx.x;
    if (k == 0) g_rcnt = 0;
    if (k >= KTOT) return;
    const float4* e4 = reinterpret_cast<const float4*>(emb + (size_t)k * D);
    float s0 = 0.f, s1 = 0.f, s2 = 0.f, s3 = 0.f;
#pragma unroll
    for (int i = 0; i < D / 4; i++) {
        float4 v = e4[i];
        s0 = fmaf(v.x, v.x, s0);
        s1 = fmaf(v.y, v.y, s1);
        s2 = fmaf(v.z, v.z, s2);
        s3 = fmaf(v.w, v.w, s3);
    }
    g_nh[k] = -0.5f * ((s0 + s1) + (s2 + s3));
}

// ---------------------------------------------------------------------------
// top-2 update (ascending idx order per thread; strict > => lowest idx wins)
// ---------------------------------------------------------------------------
__device__ __forceinline__ void upd(float& b1, float& b2, int& i1, float v, int idx) {
    if (v > b1) { b2 = b1; b1 = v; i1 = idx; }
    else        { b2 = fmaxf(b2, v); }
}
__device__ __forceinline__ void mergepair(float& b1, float& b2, int& i1, unsigned m) {
    float ob1 = __shfl_xor_sync(0xffffffffu, b1, m);
    float ob2 = __shfl_xor_sync(0xffffffffu, b2, m);
    int   oi1 = __shfl_xor_sync(0xffffffffu, i1, m);
    if (ob1 > b1 || (ob1 == b1 && oi1 < i1)) { b2 = fmaxf(b1, ob2); b1 = ob1; i1 = oi1; }
    else                                     { b2 = fmaxf(b2, ob1); }
}

// ---------------------------------------------------------------------------
// Main kernel: 256 rows/block, 8 warps, 32 rows/warp (2 m-tiles share each
// B fragment). x is split to bf16 planes in-kernel (A round trip removed).
// ---------------------------------------------------------------------------
__global__ void __launch_bounds__(256, 1) vq_mma_kernel(const float* __restrict__ inp) {
    extern __shared__ __align__(16) char smem[];
    const uint32_t SB  = smem_u32(smem);
    const int tid  = threadIdx.x;
    const int lane = tid & 31;
    const int wid  = tid >> 5;
    const int row0blk = blockIdx.x * M_BLK;

    const uint32_t smA = SB + SM_A;
    const uint32_t smB[2] = { SB + SM_B0, SB + SM_B1 };
    float* nhbuf[2] = { (float*)(smem + SM_NH0), (float*)(smem + SM_NH1) };

    // ---- prologue: prefetch B subtile 0 (async), then split A into smem ----
    {
        const char* gB = (const char*)g_B;
#pragma unroll
        for (int i = tid; i < 64 * 24; i += 256) {
            int r = i / 24, c = i - r * 24;
            cpa16(smB[0] + r * SA_BYTES + c * 16, gB + (size_t)r * 384 + c * 16);
        }
        if (tid < 64) nhbuf[0][tid] = g_nh[tid];
        CP_COMMIT();

        // in-kernel x split: 256 rows x 32 float2 -> smem planes [X0|X0|X1]
        const float2* xin = reinterpret_cast<const float2*>(inp + (size_t)row0blk * D);
#pragma unroll
        for (int i = tid; i < M_BLK * 32; i += 256) {
            int r = i >> 5, d2 = i & 31;
            float2 v = xin[i];
            unsigned short a0, a1, b0, b1;
            split2(v.x, a0, a1);
            split2(v.y, b0, b1);
            unsigned p0 = (unsigned)a0 | ((unsigned)b0 << 16);
            unsigned p1 = (unsigned)a1 | ((unsigned)b1 << 16);
            unsigned* rowp = reinterpret_cast<unsigned*>(smem + SM_A + r * SA_BYTES);
            rowp[d2]      = p0;
            rowp[32 + d2] = p0;
            rowp[64 + d2] = p1;
        }
        CP_WAIT0();
        __syncthreads();
    }

    // ldmatrix address components
    const uint32_t aAddr0 = smA + (wid * 32 + (lane & 15)) * SA_BYTES + (lane >> 4) * 16;
    const uint32_t aAddr1 = aAddr0 + 16 * SA_BYTES;
    const int q       = lane >> 3;
    const int brow    = ((q >> 1) * 8) + (lane & 7);
    const uint32_t bk = (q & 1) * 16;

    // top-2 state for the 4 rows this thread touches
    float b1r[4], b2r[4];
    int   i1r[4];
#pragma unroll
    for (int r = 0; r < 4; r++) { b1r[r] = b2r[r] = -3.402823466e+38f; i1r[r] = 0; }

    for (int s = 0; s < NSUBS; s++) {
        const int buf = s & 1;
        if (s + 1 < NSUBS) {
            const char* gB = (const char*)(g_B + (size_t)(s + 1) * 64 * 96);
#pragma unroll
            for (int i = tid; i < 64 * 24; i += 256) {
                int r = i / 24, c = i - r * 24;
                cpa16(smB[buf ^ 1] + r * SA_BYTES + c * 16, gB + (size_t)r * 384 + c * 16);
            }
            if (tid < 64) nhbuf[buf ^ 1][tid] = g_nh[(s + 1) * 64 + tid];
            CP_COMMIT();
        }

        // ---- compute: 12 k-steps x (2 m-tiles x 8 n8-tiles) ----
        float c[2][8][4];
#pragma unroll
        for (int mt = 0; mt < 2; mt++)
#pragma unroll
            for (int j = 0; j < 8; j++)
                c[mt][j][0] = c[mt][j][1] = c[mt][j][2] = c[mt][j][3] = 0.f;

        const uint32_t bb = smB[buf];
#pragma unroll
        for (int k = 0; k < 12; k++) {
            uint32_t a0, a1, a2, a3, a4, a5, a6, a7;
            LDSM4(a0, a1, a2, a3, aAddr0 + k * 32);
            LDSM4(a4, a5, a6, a7, aAddr1 + k * 32);
#pragma unroll
            for (int t = 0; t < 4; t++) {
                uint32_t r0, r1, r2, r3;
                LDSM4(r0, r1, r2, r3, bb + (t * 16 + brow) * SA_BYTES + bk + k * 32);
                MMA16816(c[0][2 * t],     a0, a1, a2, a3, r0, r1);
                MMA16816(c[0][2 * t + 1], a0, a1, a2, a3, r2, r3);
                MMA16816(c[1][2 * t],     a4, a5, a6, a7, r0, r1);
                MMA16816(c[1][2 * t + 1], a4, a5, a6, a7, r2, r3);
            }
        }

        // ---- epilogue: add nh, update top-2 (cols ascending) ----
        const float* snh = nhbuf[buf];
        const int cb = s * NSUB;
#pragma unroll
        for (int j = 0; j < 8; j++) {
            const int lc = j * 8 + 2 * (lane & 3);
            const float nh0 = snh[lc], nh1 = snh[lc + 1];
            const int gi = cb + lc;
            upd(b1r[0], b2r[0], i1r[0], c[0][j][0] + nh0, gi);
            upd(b1r[0], b2r[0], i1r[0], c[0][j][1] + nh1, gi + 1);
            upd(b1r[1], b2r[1], i1r[1], c[0][j][2] + nh0, gi);
            upd(b1r[1], b2r[1], i1r[1], c[0][j][3] + nh1, gi + 1);
            upd(b1r[2], b2r[2], i1r[2], c[1][j][0] + nh0, gi);
            upd(b1r[2], b2r[2], i1r[2], c[1][j][1] + nh1, gi + 1);
            upd(b1r[3], b2r[3], i1r[3], c[1][j][2] + nh0, gi);
            upd(b1r[3], b2r[3], i1r[3], c[1][j][3] + nh1, gi + 1);
        }

        if (s + 1 < NSUBS) {
            CP_WAIT0();
            __syncthreads();
        }
    }

    // ---- merge top-2 across the 4 lanes sharing each row ----
#pragma unroll
    for (int r = 0; r < 4; r++) {
        mergepair(b1r[r], b2r[r], i1r[r], 1);
        mergepair(b1r[r], b2r[r], i1r[r], 2);
    }

    if ((lane & 3) == 0) {
        const int base = row0blk + wid * 32 + (lane >> 2);
        const int rofs[4] = { 0, 8, 16, 24 };
#pragma unroll
        for (int r = 0; r < 4; r++) {
            const int row = base + rofs[r];
            g_bi[row] = i1r[r];
            if (b1r[r] - b2r[r] < THRESH) {
                int p = atomicAdd(&g_rcnt, 1);
                g_rlist[p] = row;
            }
        }
    }
}

// ---------------------------------------------------------------------------
// Rescue: exact fp32 full rescan for flagged rows (warp per row)
// ---------------------------------------------------------------------------
#define RES_BLOCKS 256
__global__ void __launch_bounds__(256)
vq_rescue_kernel(const float* __restrict__ inp, const float* __restrict__ emb) {
    const int lane = threadIdx.x & 31;
    const int gw   = (blockIdx.x * blockDim.x + threadIdx.x) >> 5;
    const int nw   = RES_BLOCKS * 256 / 32;
    const int cnt  = g_rcnt;

    for (int i = gw; i < cnt; i += nw) {
        const int row = g_rlist[i];
        float4 x[16];
        const float4* xr = reinterpret_cast<const float4*>(inp + (size_t)row * D);
#pragma unroll
        for (int j = 0; j < 16; j++) x[j] = xr[j];

        float best = -3.402823466e+38f;
        int   bi   = 0;
        for (int k = lane; k < KTOT; k += 32) {
            const float4* er = reinterpret_cast<const float4*>(emb + (size_t)k * D);
            float d0 = 0.f, d1 = 0.f, d2 = 0.f, d3 = 0.f;
#pragma unroll
            for (int j = 0; j < 16; j++) {
                float4 e = er[j];
                d0 = fmaf(x[j].x, e.x, d0);
                d1 = fmaf(x[j].y, e.y, d1);
                d2 = fmaf(x[j].z, e.z, d2);
                d3 = fmaf(x[j].w, e.w, d3);
            }
            float sc = ((d0 + d1) + (d2 + d3)) + g_nh[k];
            if (sc > best) { best = sc; bi = k; }   // ascending per lane
        }
#pragma unroll
        for (int m = 16; m >= 1; m >>= 1) {
            float ob = __shfl_xor_sync(0xffffffffu, best, m);
            int   oi = __shfl_xor_sync(0xffffffffu, bi, m);
            if (ob > best || (ob == best && oi < bi)) { best = ob; bi = oi; }
        }
        if (lane == 0) g_bi[row] = bi;
    }
}

// ---------------------------------------------------------------------------
// Combine: emit all three outputs, fully coalesced (16 threads per row)
// ---------------------------------------------------------------------------
__global__ void __launch_bounds__(256)
vq_combine_kernel(const float* __restrict__ inp,
                  const float* __restrict__ emb,
                  float* __restrict__ out) {
    const int t   = blockIdx.x * blockDim.x + threadIdx.x;   // NROWS*16
    const int row = t >> 4;
    const int c   = t & 15;
    const int bi  = g_bi[row];

    const float4 qv = reinterpret_cast<const float4*>(emb + (size_t)bi * D)[c];
    reinterpret_cast<float4*>(out + (size_t)row * D)[c] = qv;

    const float4 xi = reinterpret_cast<const float4*>(inp + (size_t)row * D)[c];
    reinterpret_cast<float4*>(out + OFF_FLAT + (size_t)row * D)[c] = xi;

    if (c == 0) out[OFF_IDX + row] = (float)bi;
}

// ---------------------------------------------------------------------------
extern "C" void kernel_launch(void* const* d_in, const int* in_sizes, int n_in,
                              void* d_out, int out_size) {
    const float* inp = (const float*)d_in[0];   // [64,32,32,64] fp32
    const float* emb = (const float*)d_in[1];   // [2048,64]     fp32
    float* out = (float*)d_out;

    static int smem_set = 0;
    if (!smem_set) {
        cudaFuncSetAttribute(vq_mma_kernel,
                             cudaFuncAttributeMaxDynamicSharedMemorySize, SMEM_TOTAL);
        smem_set = 1;
    }

    vq_split_e<<<KTOT * 32 / 256, 256>>>(emb);
    vq_nh_kernel<<<(KTOT + 255) / 256, 256>>>(emb);
    vq_mma_kernel<<<NBLOCKS, 256, SMEM_TOTAL>>>(inp);
    vq_rescue_kernel<<<RES_BLOCKS, 256>>>(inp, emb);
    vq_combine_kernel<<<NROWS * 16 / 256, 256>>>(inp, emb, out);
}